// round 3
// baseline (speedup 1.0000x reference)
#include <cuda_runtime.h>

#define Bn 64
#define Nn 512
#define Kk 32
#define Dd 64
#define BN_TOTAL (Bn*Nn)   // 32768
#define EPSf 1e-5f
#define NEG_SLOPE 0.2f
#define NEG_INFf -1e9f

// ---- scratch (static device globals; no allocation) ----
__device__ float g_nrm[Nn];
__device__ float g_edot_i[Nn];
__device__ float g_edot_j[Nn];
__device__ int   g_topk[Nn * Kk];
__device__ float g_xl[(size_t)BN_TOTAL * Dd];   // 8 MB
__device__ float g_ci[BN_TOTAL];
__device__ float g_cj[BN_TOTAL];

// ---- f32x2 packed helpers ----
__device__ __forceinline__ unsigned long long fma2(unsigned long long a,
                                                   unsigned long long b,
                                                   unsigned long long c) {
    unsigned long long d;
    asm("fma.rn.f32x2 %0, %1, %2, %3;" : "=l"(d) : "l"(a), "l"(b), "l"(c));
    return d;
}
__device__ __forceinline__ unsigned long long dup2(float x) {
    unsigned long long d; unsigned int u = __float_as_uint(x);
    asm("mov.b64 %0, {%1, %2};" : "=l"(d) : "r"(u), "r"(u));
    return d;
}
__device__ __forceinline__ float2 unpack2(unsigned long long v) {
    unsigned int lo, hi;
    asm("mov.b64 {%0, %1}, %2;" : "=r"(lo), "=r"(hi) : "l"(v));
    return make_float2(__uint_as_float(lo), __uint_as_float(hi));
}

// ---------------------------------------------------------------
// Kernel 1: per-embedding-row norm and dot products with att_em_{i,j}
// ---------------------------------------------------------------
__global__ void k_norms(const float* __restrict__ emb,
                        const float* __restrict__ att_em_i,
                        const float* __restrict__ att_em_j) {
    int n = blockIdx.x * blockDim.x + threadIdx.x;
    if (n >= Nn) return;
    const float* row = emb + n * Dd;
    float s2 = 0.f, di = 0.f, dj = 0.f;
#pragma unroll 8
    for (int d = 0; d < Dd; d++) {
        float e = row[d];
        s2 += e * e;
        di += e * att_em_i[d];
        dj += e * att_em_j[d];
    }
    g_nrm[n]    = sqrtf(s2);
    g_edot_i[n] = di;
    g_edot_j[n] = dj;
}

// ---------------------------------------------------------------
// Kernel 2: cosine top-K, TWO rows per warp (halves emb traffic and
// interleaves the two rows' argmax chains to hide shuffle latency).
// Tie-break: smaller index wins (matches jax.lax.top_k).
// ---------------------------------------------------------------
__global__ void __launch_bounds__(64)
k_topk(const float* __restrict__ emb) {
    __shared__ float s_ra[2][Dd];
    __shared__ float s_rb[2][Dd];

    const int w = threadIdx.x >> 5;
    const int t = threadIdx.x & 31;
    const int ia = blockIdx.x * 4 + w * 2;
    const int ib = ia + 1;

    {   // stage the two target rows
        float2 va = ((const float2*)(emb + ia * Dd))[t];
        float2 vb = ((const float2*)(emb + ib * Dd))[t];
        s_ra[w][2 * t] = va.x; s_ra[w][2 * t + 1] = va.y;
        s_rb[w][2 * t] = vb.x; s_rb[w][2 * t + 1] = vb.y;
    }
    __syncwarp();

    const float inv_a = 1.0f / g_nrm[ia];
    const float inv_b = 1.0f / g_nrm[ib];
    const float4* ra4 = (const float4*)s_ra[w];
    const float4* rb4 = (const float4*)s_rb[w];

    unsigned long long keya[16], keyb[16];
#pragma unroll
    for (int m = 0; m < 16; m++) {
        const int j = 32 * m + t;
        const float4* rj = (const float4*)(emb + j * Dd);
        float da = 0.f, db = 0.f;
#pragma unroll
        for (int q = 0; q < 16; q++) {
            float4 v = rj[q];
            float4 a = ra4[q], b = rb4[q];
            da += v.x * a.x + v.y * a.y + v.z * a.z + v.w * a.w;
            db += v.x * b.x + v.y * b.y + v.z * b.z + v.w * b.w;
        }
        const float invj = 1.0f / g_nrm[j];
        float ca = da * inv_a * invj;
        float cb = db * inv_b * invj;
        unsigned int bitsa = __float_as_uint(ca);
        bitsa = (bitsa & 0x80000000u) ? ~bitsa : (bitsa | 0x80000000u);
        unsigned int bitsb = __float_as_uint(cb);
        bitsb = (bitsb & 0x80000000u) ? ~bitsb : (bitsb | 0x80000000u);
        keya[m] = ((unsigned long long)bitsa << 32) | (unsigned int)(Nn - 1 - j);
        keyb[m] = ((unsigned long long)bitsb << 32) | (unsigned int)(Nn - 1 - j);
    }

    for (int k = 0; k < Kk; k++) {
        unsigned long long ba = 0ull, bb = 0ull;
#pragma unroll
        for (int m = 0; m < 16; m++) {
            ba = (keya[m] > ba) ? keya[m] : ba;
            bb = (keyb[m] > bb) ? keyb[m] : bb;
        }
#pragma unroll
        for (int o = 16; o > 0; o >>= 1) {
            unsigned long long va = __shfl_xor_sync(0xFFFFFFFFu, ba, o);
            unsigned long long vb = __shfl_xor_sync(0xFFFFFFFFu, bb, o);
            ba = (va > ba) ? va : ba;
            bb = (vb > bb) ? vb : bb;
        }
#pragma unroll
        for (int m = 0; m < 16; m++) {
            if (keya[m] == ba) keya[m] = 0ull;
            if (keyb[m] == bb) keyb[m] = 0ull;
        }
        if (t == 0) {
            g_topk[ia * Kk + k] = Nn - 1 - (int)(ba & 0xFFFFFFFFu);
            g_topk[ib * Kk + k] = Nn - 1 - (int)(bb & 0xFFFFFFFFu);
        }
    }
}

// ---------------------------------------------------------------
// Kernel 3: xl = x @ W^T and per-node scalars ci, cj.
// f32x2-packed: accumulator lanes hold a NODE PAIR; x comes from a
// transposed smem tile as a natural 8B broadcast, w duplicated once/k.
// ---------------------------------------------------------------
#define XT_STRIDE 66
__global__ void __launch_bounds__(256)
k_xl(const float* __restrict__ x,
     const float* __restrict__ W,
     const float* __restrict__ att_i,
     const float* __restrict__ att_j) {
    __shared__ float s_W[Dd][Dd + 1];        // s_W[k][d] = W[d][k]
    __shared__ float s_xt[Dd][XT_STRIDE];    // s_xt[k][n_local], 8B-aligned pairs

    const int tid = threadIdx.x;
    const int w = tid >> 5, t = tid & 31;
    const int node_blk = blockIdx.x * 64;

    for (int idx = tid; idx < Dd * Dd; idx += 256) {
        int d = idx >> 6, k = idx & 63;
        s_W[k][d] = W[idx];
    }
    {   // transposed stage of 64 input rows
        const float4* xs = (const float4*)(x + (size_t)node_blk * Dd);
#pragma unroll
        for (int v = tid; v < 1024; v += 256) {
            float4 val = xs[v];
            int n = v >> 4, q = (v & 15) * 4;
            float* dst = &s_xt[0][0] + q * XT_STRIDE + n;
            dst[0]             = val.x;
            dst[XT_STRIDE]     = val.y;
            dst[2 * XT_STRIDE] = val.z;
            dst[3 * XT_STRIDE] = val.w;
        }
    }
    __syncthreads();

    const float ai0 = att_i[t], ai1 = att_i[t + 32];
    const float aj0 = att_j[t], aj1 = att_j[t + 32];

    unsigned long long accA[4] = {0ull, 0ull, 0ull, 0ull};
    unsigned long long accB[4] = {0ull, 0ull, 0ull, 0ull};
    const int nl0 = w * 8;

#pragma unroll 16
    for (int k = 0; k < Dd; k++) {
        const unsigned long long wd0 = dup2(s_W[k][t]);
        const unsigned long long wd1 = dup2(s_W[k][t + 32]);
        const unsigned long long* xrow =
            (const unsigned long long*)(&s_xt[0][0] + k * XT_STRIDE + nl0);
#pragma unroll
        for (int p = 0; p < 4; p++) {
            const unsigned long long xp = xrow[p];   // (x[n0][k], x[n1][k]) broadcast
            accA[p] = fma2(xp, wd0, accA[p]);
            accB[p] = fma2(xp, wd1, accB[p]);
        }
    }

#pragma unroll
    for (int p = 0; p < 4; p++) {
        const float2 a = unpack2(accA[p]);   // channel t, nodes (n0, n1)
        const float2 b = unpack2(accB[p]);   // channel t+32
        const int n0 = node_blk + nl0 + 2 * p;
        const int n1 = n0 + 1;
        g_xl[(size_t)n0 * Dd + t]      = a.x;
        g_xl[(size_t)n0 * Dd + t + 32] = b.x;
        g_xl[(size_t)n1 * Dd + t]      = a.y;
        g_xl[(size_t)n1 * Dd + t + 32] = b.y;

        float pi0 = a.x * ai0 + b.x * ai1, pj0 = a.x * aj0 + b.x * aj1;
        float pi1 = a.y * ai0 + b.y * ai1, pj1 = a.y * aj0 + b.y * aj1;
#pragma unroll
        for (int o = 16; o > 0; o >>= 1) {
            pi0 += __shfl_xor_sync(0xFFFFFFFFu, pi0, o);
            pj0 += __shfl_xor_sync(0xFFFFFFFFu, pj0, o);
            pi1 += __shfl_xor_sync(0xFFFFFFFFu, pi1, o);
            pj1 += __shfl_xor_sync(0xFFFFFFFFu, pj1, o);
        }
        if (t == 0) {
            const int l0 = n0 & (Nn - 1), l1 = n1 & (Nn - 1);
            g_ci[n0] = pi0 + g_edot_i[l0];
            g_cj[n0] = pj0 + g_edot_j[l0];
            g_ci[n1] = pi1 + g_edot_i[l1];
            g_cj[n1] = pj1 + g_edot_j[l1];
        }
    }
}

// ---------------------------------------------------------------
// Kernel 4: attention + epilogue. 512 blocks x 128 threads,
// 8 blocks per batch (L1-resident xl slice), LDG.64 gather.
// ---------------------------------------------------------------
__global__ void __launch_bounds__(128)
k_attn(const float* __restrict__ emb,
       const float* __restrict__ gnn_bias,
       const float* __restrict__ bn1_gamma, const float* __restrict__ bn1_beta,
       const float* __restrict__ bn1_mean,  const float* __restrict__ bn1_var,
       const float* __restrict__ bno_gamma, const float* __restrict__ bno_beta,
       const float* __restrict__ bno_mean,  const float* __restrict__ bno_var,
       const float* __restrict__ out_W,     const float* __restrict__ out_b,
       float* __restrict__ out) {
    __shared__ float  s_cj[Nn];
    __shared__ float2 s_ws[4][32];

    const int tid = threadIdx.x;
    const int w = tid >> 5, t = tid & 31;
    const int batch = blockIdx.x >> 3;
    const int lbase = (blockIdx.x & 7) * 64;
    const int base  = batch * Nn;

    for (int q = tid; q < Nn; q += 128) s_cj[q] = g_cj[base + q];
    __syncthreads();

    // per-lane channel pair (2t, 2t+1) constants
    const float2 gb = ((const float2*)gnn_bias)[t];
    const float2 g1 = ((const float2*)bn1_gamma)[t];
    const float2 b1 = ((const float2*)bn1_beta)[t];
    const float2 m1 = ((const float2*)bn1_mean)[t];
    const float2 v1 = ((const float2*)bn1_var)[t];
    const float2 go = ((const float2*)bno_gamma)[t];
    const float2 bo = ((const float2*)bno_beta)[t];
    const float2 mo = ((const float2*)bno_mean)[t];
    const float2 vo = ((const float2*)bno_var)[t];
    const float2 ow = ((const float2*)out_W)[t];
    const float  ob = out_b[0];
    const float s10 = rsqrtf(v1.x + EPSf) * g1.x;
    const float s11 = rsqrtf(v1.y + EPSf) * g1.y;
    const float so0 = rsqrtf(vo.x + EPSf) * go.x;
    const float so1 = rsqrtf(vo.y + EPSf) * go.y;

    const float* xb = g_xl + (size_t)base * Dd;

#pragma unroll 1
    for (int r = 0; r < 16; r++) {
        const int li = lbase + w * 16 + r;
        const int node = base + li;

        const float ci = g_ci[node];
        const int srcj = g_topk[li * Kk + t];
        const bool valid = (srcj != li);

        float lg = ci + s_cj[srcj];
        lg = (lg >= 0.f) ? lg : NEG_SLOPE * lg;
        if (!valid) lg = NEG_INFf;

        float lgs = ci + s_cj[li];
        lgs = (lgs >= 0.f) ? lgs : NEG_SLOPE * lgs;

        float m = lg;
#pragma unroll
        for (int o = 16; o > 0; o >>= 1) m = fmaxf(m, __shfl_xor_sync(0xFFFFFFFFu, m, o));
        m = fmaxf(m, lgs);

        const float ex  = valid ? __expf(lg - m) : 0.0f;
        const float exs = __expf(lgs - m);
        float sum = ex;
#pragma unroll
        for (int o = 16; o > 0; o >>= 1) sum += __shfl_xor_sync(0xFFFFFFFFu, sum, o);
        sum += exs;
        const float inv = 1.0f / sum;            // warp-uniform

        s_ws[w][t] = make_float2(ex * inv, __int_as_float(srcj));
        __syncwarp();

        // self edge (warp-uniform weight)
        const float wself = exs * inv;
        float2 vs = *(const float2*)(xb + li * Dd + 2 * t);
        float acc0 = wself * vs.x, acc1 = wself * vs.y;

#pragma unroll
        for (int e = 0; e < Kk; e++) {
            const float2 ws = s_ws[w][e];        // 8B broadcast LDS
            const int se = __float_as_int(ws.y);
            const float2 v = *(const float2*)(xb + se * Dd + 2 * t);  // one LDG.64/row
            acc0 += ws.x * v.x;
            acc1 += ws.x * v.y;
        }
        __syncwarp();

        // epilogue
        const float2 em = *(const float2*)(emb + li * Dd + 2 * t);
        float h0 = acc0 + gb.x, h1 = acc1 + gb.y;
        h0 = (h0 - m1.x) * s10 + b1.x;
        h1 = (h1 - m1.y) * s11 + b1.y;
        h0 = fmaxf(h0, 0.f) * em.x;
        h1 = fmaxf(h1, 0.f) * em.y;
        h0 = (h0 - mo.x) * so0 + bo.x;
        h1 = (h1 - mo.y) * so1 + bo.y;
        h0 = fmaxf(h0, 0.f);
        h1 = fmaxf(h1, 0.f);

        float p = h0 * ow.x + h1 * ow.y;
#pragma unroll
        for (int o = 16; o > 0; o >>= 1) p += __shfl_xor_sync(0xFFFFFFFFu, p, o);
        if (t == 0) out[node] = p + ob;
    }
}

// ---------------------------------------------------------------
extern "C" void kernel_launch(void* const* d_in, const int* in_sizes, int n_in,
                              void* d_out, int out_size) {
    (void)in_sizes; (void)n_in; (void)out_size;
    const float* data      = (const float*)d_in[0];
    /* d_in[1] = org_edge_index — unused by the model */
    const float* emb       = (const float*)d_in[2];
    const float* lin_W     = (const float*)d_in[3];
    const float* att_i     = (const float*)d_in[4];
    const float* att_j     = (const float*)d_in[5];
    const float* att_em_i  = (const float*)d_in[6];
    const float* att_em_j  = (const float*)d_in[7];
    const float* gnn_bias  = (const float*)d_in[8];
    const float* bn1_gamma = (const float*)d_in[9];
    const float* bn1_beta  = (const float*)d_in[10];
    const float* bn1_mean  = (const float*)d_in[11];
    const float* bn1_var   = (const float*)d_in[12];
    const float* bno_gamma = (const float*)d_in[13];
    const float* bno_beta  = (const float*)d_in[14];
    const float* bno_mean  = (const float*)d_in[15];
    const float* bno_var   = (const float*)d_in[16];
    const float* out_W     = (const float*)d_in[17];
    const float* out_b     = (const float*)d_in[18];
    float* out = (float*)d_out;

    k_norms<<<2, 256>>>(emb, att_em_i, att_em_j);
    k_topk<<<Nn / 4, 64>>>(emb);
    k_xl<<<BN_TOTAL / 64, 256>>>(data, lin_W, att_i, att_j);
    k_attn<<<BN_TOTAL / 64, 128>>>(emb, gnn_bias,
                                   bn1_gamma, bn1_beta, bn1_mean, bn1_var,
                                   bno_gamma, bno_beta, bno_mean, bno_var,
                                   out_W, out_b, out);
}

// round 4
// speedup vs baseline: 1.5973x; 1.5973x over previous
#include <cuda_runtime.h>

#define Bn 64
#define Nn 512
#define Kk 32
#define Dd 64
#define BN_TOTAL (Bn*Nn)   // 32768
#define EPSf 1e-5f
#define NEG_SLOPE 0.2f
#define NEG_INFf -1e9f

// ---- scratch (static device globals; no allocation) ----
__device__ float g_invn[Nn];
__device__ float g_edot_i[Nn];
__device__ float g_edot_j[Nn];
__device__ float g_cos[Nn * Nn];                // 1 MB
__device__ int   g_topk[Nn * Kk];
__device__ float g_xl[(size_t)BN_TOTAL * Dd];   // 8 MB
__device__ float g_ci[BN_TOTAL];
__device__ float g_cj[BN_TOTAL];

// ---- f32x2 packed helpers ----
__device__ __forceinline__ unsigned long long fma2(unsigned long long a,
                                                   unsigned long long b,
                                                   unsigned long long c) {
    unsigned long long d;
    asm("fma.rn.f32x2 %0, %1, %2, %3;" : "=l"(d) : "l"(a), "l"(b), "l"(c));
    return d;
}
__device__ __forceinline__ unsigned long long dup2(float x) {
    unsigned long long d; unsigned int u = __float_as_uint(x);
    asm("mov.b64 %0, {%1, %2};" : "=l"(d) : "r"(u), "r"(u));
    return d;
}
__device__ __forceinline__ float2 unpack2(unsigned long long v) {
    unsigned int lo, hi;
    asm("mov.b64 {%0, %1}, %2;" : "=r"(lo), "=r"(hi) : "l"(v));
    return make_float2(__uint_as_float(lo), __uint_as_float(hi));
}

// ---------------------------------------------------------------
// Kernel 1: inverse norm + dot products with att_em_{i,j}
// ---------------------------------------------------------------
__global__ void k_norms(const float* __restrict__ emb,
                        const float* __restrict__ att_em_i,
                        const float* __restrict__ att_em_j) {
    int n = blockIdx.x * blockDim.x + threadIdx.x;
    if (n >= Nn) return;
    const float* row = emb + n * Dd;
    float s2 = 0.f, di = 0.f, dj = 0.f;
#pragma unroll 8
    for (int d = 0; d < Dd; d++) {
        float e = row[d];
        s2 += e * e;
        di += e * att_em_i[d];
        dj += e * att_em_j[d];
    }
    g_invn[n]   = rsqrtf(s2);
    g_edot_i[n] = di;
    g_edot_j[n] = dj;
}

// ---------------------------------------------------------------
// Kernel 2: cos = diag(1/n) (E E^T) diag(1/n), tiled GEMM.
// Block = 32(i) x 64(j) tile; 256 threads; fully coalesced.
// ---------------------------------------------------------------
__global__ void __launch_bounds__(256)
k_cos(const float* __restrict__ emb) {
    __shared__ float s_A[32][65];
    __shared__ float s_B[64][65];

    const int tid = threadIdx.x;
    const int w = tid >> 5, t = tid & 31;
    const int i0 = blockIdx.y * 32;
    const int j0 = blockIdx.x * 64;

    for (int idx = tid; idx < 32 * 32; idx += 256) {     // A tile (float2 units)
        int r = idx >> 5, c = idx & 31;
        float2 v = ((const float2*)(emb + (i0 + r) * Dd))[c];
        s_A[r][2 * c] = v.x; s_A[r][2 * c + 1] = v.y;
    }
    for (int idx = tid; idx < 64 * 32; idx += 256) {     // B tile
        int r = idx >> 5, c = idx & 31;
        float2 v = ((const float2*)(emb + (j0 + r) * Dd))[c];
        s_B[r][2 * c] = v.x; s_B[r][2 * c + 1] = v.y;
    }
    __syncthreads();

    float acc[4][2] = {};
#pragma unroll 8
    for (int k = 0; k < Dd; k++) {
        const float b0 = s_B[t][k];          // bank (t+k)%32 conflict-free
        const float b1 = s_B[t + 32][k];
#pragma unroll
        for (int a = 0; a < 4; a++) {
            const float av = s_A[w * 4 + a][k];   // warp-uniform broadcast
            acc[a][0] += av * b0;
            acc[a][1] += av * b1;
        }
    }

    const float invj0 = g_invn[j0 + t];
    const float invj1 = g_invn[j0 + t + 32];
#pragma unroll
    for (int a = 0; a < 4; a++) {
        const int irow = i0 + w * 4 + a;
        const float inv_i = g_invn[irow];
        g_cos[irow * Nn + j0 + t]      = acc[a][0] * inv_i * invj0;
        g_cos[irow * Nn + j0 + t + 32] = acc[a][1] * inv_i * invj1;
    }
}

// ---------------------------------------------------------------
// Kernel 3: top-K per row from g_cos (coalesced reads), warp/row.
// 32 shuffle-argmax rounds; tie-break = smaller index.
// ---------------------------------------------------------------
__global__ void __launch_bounds__(128)
k_topk() {
    const int w = threadIdx.x >> 5;
    const int t = threadIdx.x & 31;
    const int i = blockIdx.x * 4 + w;
    const float* crow = g_cos + i * Nn;

    unsigned long long key[16];
#pragma unroll
    for (int m = 0; m < 16; m++) {
        const int j = 32 * m + t;
        unsigned int bits = __float_as_uint(crow[j]);   // coalesced 128B
        bits = (bits & 0x80000000u) ? ~bits : (bits | 0x80000000u);
        key[m] = ((unsigned long long)bits << 32) | (unsigned int)(Nn - 1 - j);
    }

    for (int k = 0; k < Kk; k++) {
        unsigned long long best = 0ull;
#pragma unroll
        for (int m = 0; m < 16; m++) best = (key[m] > best) ? key[m] : best;
#pragma unroll
        for (int o = 16; o > 0; o >>= 1) {
            unsigned long long v = __shfl_xor_sync(0xFFFFFFFFu, best, o);
            best = (v > best) ? v : best;
        }
#pragma unroll
        for (int m = 0; m < 16; m++) if (key[m] == best) key[m] = 0ull;
        if (t == 0) g_topk[i * Kk + k] = Nn - 1 - (int)(best & 0xFFFFFFFFu);
    }
}

// ---------------------------------------------------------------
// Kernel 4: xl = x @ W^T and per-node scalars ci, cj (f32x2 packed).
// ---------------------------------------------------------------
#define XT_STRIDE 66
__global__ void __launch_bounds__(256)
k_xl(const float* __restrict__ x,
     const float* __restrict__ W,
     const float* __restrict__ att_i,
     const float* __restrict__ att_j) {
    __shared__ float s_W[Dd][Dd + 1];        // s_W[k][d] = W[d][k]
    __shared__ float s_xt[Dd][XT_STRIDE];    // s_xt[k][n_local]

    const int tid = threadIdx.x;
    const int w = tid >> 5, t = tid & 31;
    const int node_blk = blockIdx.x * 64;

    for (int idx = tid; idx < Dd * Dd; idx += 256) {
        int d = idx >> 6, k = idx & 63;
        s_W[k][d] = W[idx];
    }
    {
        const float4* xs = (const float4*)(x + (size_t)node_blk * Dd);
#pragma unroll
        for (int v = tid; v < 1024; v += 256) {
            float4 val = xs[v];
            int n = v >> 4, q = (v & 15) * 4;
            float* dst = &s_xt[0][0] + q * XT_STRIDE + n;
            dst[0]             = val.x;
            dst[XT_STRIDE]     = val.y;
            dst[2 * XT_STRIDE] = val.z;
            dst[3 * XT_STRIDE] = val.w;
        }
    }
    __syncthreads();

    const float ai0 = att_i[t], ai1 = att_i[t + 32];
    const float aj0 = att_j[t], aj1 = att_j[t + 32];

    unsigned long long accA[4] = {0ull, 0ull, 0ull, 0ull};
    unsigned long long accB[4] = {0ull, 0ull, 0ull, 0ull};
    const int nl0 = w * 8;

#pragma unroll 16
    for (int k = 0; k < Dd; k++) {
        const unsigned long long wd0 = dup2(s_W[k][t]);
        const unsigned long long wd1 = dup2(s_W[k][t + 32]);
        const unsigned long long* xrow =
            (const unsigned long long*)(&s_xt[0][0] + k * XT_STRIDE + nl0);
#pragma unroll
        for (int p = 0; p < 4; p++) {
            const unsigned long long xp = xrow[p];
            accA[p] = fma2(xp, wd0, accA[p]);
            accB[p] = fma2(xp, wd1, accB[p]);
        }
    }

#pragma unroll
    for (int p = 0; p < 4; p++) {
        const float2 a = unpack2(accA[p]);
        const float2 b = unpack2(accB[p]);
        const int n0 = node_blk + nl0 + 2 * p;
        const int n1 = n0 + 1;
        g_xl[(size_t)n0 * Dd + t]      = a.x;
        g_xl[(size_t)n0 * Dd + t + 32] = b.x;
        g_xl[(size_t)n1 * Dd + t]      = a.y;
        g_xl[(size_t)n1 * Dd + t + 32] = b.y;

        float pi0 = a.x * ai0 + b.x * ai1, pj0 = a.x * aj0 + b.x * aj1;
        float pi1 = a.y * ai0 + b.y * ai1, pj1 = a.y * aj0 + b.y * aj1;
#pragma unroll
        for (int o = 16; o > 0; o >>= 1) {
            pi0 += __shfl_xor_sync(0xFFFFFFFFu, pi0, o);
            pj0 += __shfl_xor_sync(0xFFFFFFFFu, pj0, o);
            pi1 += __shfl_xor_sync(0xFFFFFFFFu, pi1, o);
            pj1 += __shfl_xor_sync(0xFFFFFFFFu, pj1, o);
        }
        if (t == 0) {
            const int l0 = n0 & (Nn - 1), l1 = n1 & (Nn - 1);
            g_ci[n0] = pi0 + g_edot_i[l0];
            g_cj[n0] = pj0 + g_edot_j[l0];
            g_ci[n1] = pi1 + g_edot_i[l1];
            g_cj[n1] = pj1 + g_edot_j[l1];
        }
    }
}

// ---------------------------------------------------------------
// Kernel 5: attention + epilogue.
// 2048 blocks x 256 threads (8 warps, 2 targets/warp) -> ~16K warps
// for full latency hiding. LDG.64 gather + FFMA2; BN folded.
// ---------------------------------------------------------------
__global__ void __launch_bounds__(256)
k_attn(const float* __restrict__ emb,
       const float* __restrict__ gnn_bias,
       const float* __restrict__ bn1_gamma, const float* __restrict__ bn1_beta,
       const float* __restrict__ bn1_mean,  const float* __restrict__ bn1_var,
       const float* __restrict__ bno_gamma, const float* __restrict__ bno_beta,
       const float* __restrict__ bno_mean,  const float* __restrict__ bno_var,
       const float* __restrict__ out_W,     const float* __restrict__ out_b,
       float* __restrict__ out) {
    __shared__ float  s_cj[Nn];
    __shared__ float2 s_ws[8][2][32];

    const int tid = threadIdx.x;
    const int w = tid >> 5, t = tid & 31;
    const int batch = blockIdx.x >> 5;
    const int lbase = (blockIdx.x & 31) * 16;
    const int base  = batch * Nn;

    s_cj[tid]       = g_cj[base + tid];
    s_cj[tid + 256] = g_cj[base + tid + 256];
    __syncthreads();

    // folded per-lane constants for channel pair (2t, 2t+1)
    const float2 gb = ((const float2*)gnn_bias)[t];
    const float2 g1 = ((const float2*)bn1_gamma)[t];
    const float2 b1 = ((const float2*)bn1_beta)[t];
    const float2 m1 = ((const float2*)bn1_mean)[t];
    const float2 v1 = ((const float2*)bn1_var)[t];
    const float2 go = ((const float2*)bno_gamma)[t];
    const float2 bo = ((const float2*)bno_beta)[t];
    const float2 mo = ((const float2*)bno_mean)[t];
    const float2 vo = ((const float2*)bno_var)[t];
    const float2 ow = ((const float2*)out_W)[t];
    const float  ob = out_b[0];
    const float s1x = rsqrtf(v1.x + EPSf) * g1.x;
    const float s1y = rsqrtf(v1.y + EPSf) * g1.y;
    const float C1x = (gb.x - m1.x) * s1x + b1.x;   // h = acc*s1 + C1
    const float C1y = (gb.y - m1.y) * s1y + b1.y;
    const float sox = rsqrtf(vo.x + EPSf) * go.x;
    const float soy = rsqrtf(vo.y + EPSf) * go.y;
    const float Cox = bo.x - mo.x * sox;            // u = v*so + Co
    const float Coy = bo.y - mo.y * soy;

    const int li0 = lbase + 2 * w, li1 = li0 + 1;
    const int node0 = base + li0,  node1 = base + li1;

    const float ci0 = g_ci[node0];
    const float ci1 = g_ci[node1];
    const int s0 = g_topk[li0 * Kk + t];
    const int s1 = g_topk[li1 * Kk + t];
    const bool v0ok = (s0 != li0);
    const bool v1ok = (s1 != li1);

    float lg0 = ci0 + s_cj[s0];
    float lg1 = ci1 + s_cj[s1];
    lg0 = (lg0 >= 0.f) ? lg0 : NEG_SLOPE * lg0;
    lg1 = (lg1 >= 0.f) ? lg1 : NEG_SLOPE * lg1;
    if (!v0ok) lg0 = NEG_INFf;
    if (!v1ok) lg1 = NEG_INFf;

    float lgs0 = ci0 + s_cj[li0];
    float lgs1 = ci1 + s_cj[li1];
    lgs0 = (lgs0 >= 0.f) ? lgs0 : NEG_SLOPE * lgs0;
    lgs1 = (lgs1 >= 0.f) ? lgs1 : NEG_SLOPE * lgs1;

    float mx0 = lg0, mx1 = lg1;
#pragma unroll
    for (int o = 16; o > 0; o >>= 1) {
        mx0 = fmaxf(mx0, __shfl_xor_sync(0xFFFFFFFFu, mx0, o));
        mx1 = fmaxf(mx1, __shfl_xor_sync(0xFFFFFFFFu, mx1, o));
    }
    mx0 = fmaxf(mx0, lgs0);
    mx1 = fmaxf(mx1, lgs1);

    const float ex0  = v0ok ? __expf(lg0 - mx0) : 0.0f;
    const float ex1  = v1ok ? __expf(lg1 - mx1) : 0.0f;
    const float exs0 = __expf(lgs0 - mx0);
    const float exs1 = __expf(lgs1 - mx1);
    float sum0 = ex0, sum1 = ex1;
#pragma unroll
    for (int o = 16; o > 0; o >>= 1) {
        sum0 += __shfl_xor_sync(0xFFFFFFFFu, sum0, o);
        sum1 += __shfl_xor_sync(0xFFFFFFFFu, sum1, o);
    }
    const float inv0 = 1.0f / (sum0 + exs0);
    const float inv1 = 1.0f / (sum1 + exs1);

    s_ws[w][0][t] = make_float2(ex0 * inv0, __int_as_float(s0));
    s_ws[w][1][t] = make_float2(ex1 * inv1, __int_as_float(s1));
    __syncwarp();

    const float* xb = g_xl + (size_t)base * Dd;
    // self edges (warp-uniform weights)
    unsigned long long a0 = fma2(*(const unsigned long long*)(xb + li0 * Dd + 2 * t),
                                 dup2(exs0 * inv0), 0ull);
    unsigned long long a1 = fma2(*(const unsigned long long*)(xb + li1 * Dd + 2 * t),
                                 dup2(exs1 * inv1), 0ull);
#pragma unroll 8
    for (int e = 0; e < Kk; e++) {
        const float2 w0 = s_ws[w][0][e];
        const float2 w1 = s_ws[w][1][e];
        const unsigned long long r0 =
            *(const unsigned long long*)(xb + __float_as_int(w0.y) * Dd + 2 * t);
        const unsigned long long r1 =
            *(const unsigned long long*)(xb + __float_as_int(w1.y) * Dd + 2 * t);
        a0 = fma2(r0, dup2(w0.x), a0);
        a1 = fma2(r1, dup2(w1.x), a1);
    }
    __syncwarp();

    // epilogue, both targets
    const float2 em0 = *(const float2*)(emb + li0 * Dd + 2 * t);
    const float2 em1 = *(const float2*)(emb + li1 * Dd + 2 * t);
    const float2 A0 = unpack2(a0);
    const float2 A1 = unpack2(a1);

    float h00 = fmaxf(fmaf(A0.x, s1x, C1x), 0.f) * em0.x;
    float h01 = fmaxf(fmaf(A0.y, s1y, C1y), 0.f) * em0.y;
    float h10 = fmaxf(fmaf(A1.x, s1x, C1x), 0.f) * em1.x;
    float h11 = fmaxf(fmaf(A1.y, s1y, C1y), 0.f) * em1.y;
    h00 = fmaxf(fmaf(h00, sox, Cox), 0.f);
    h01 = fmaxf(fmaf(h01, soy, Coy), 0.f);
    h10 = fmaxf(fmaf(h10, sox, Cox), 0.f);
    h11 = fmaxf(fmaf(h11, soy, Coy), 0.f);

    float p0 = h00 * ow.x + h01 * ow.y;
    float p1 = h10 * ow.x + h11 * ow.y;
#pragma unroll
    for (int o = 16; o > 0; o >>= 1) {
        p0 += __shfl_xor_sync(0xFFFFFFFFu, p0, o);
        p1 += __shfl_xor_sync(0xFFFFFFFFu, p1, o);
    }
    if (t == 0) {
        out[node0] = p0 + ob;
        out[node1] = p1 + ob;
    }
}

// ---------------------------------------------------------------
extern "C" void kernel_launch(void* const* d_in, const int* in_sizes, int n_in,
                              void* d_out, int out_size) {
    (void)in_sizes; (void)n_in; (void)out_size;
    const float* data      = (const float*)d_in[0];
    /* d_in[1] = org_edge_index — unused by the model */
    const float* emb       = (const float*)d_in[2];
    const float* lin_W     = (const float*)d_in[3];
    const float* att_i     = (const float*)d_in[4];
    const float* att_j     = (const float*)d_in[5];
    const float* att_em_i  = (const float*)d_in[6];
    const float* att_em_j  = (const float*)d_in[7];
    const float* gnn_bias  = (const float*)d_in[8];
    const float* bn1_gamma = (const float*)d_in[9];
    const float* bn1_beta  = (const float*)d_in[10];
    const float* bn1_mean  = (const float*)d_in[11];
    const float* bn1_var   = (const float*)d_in[12];
    const float* bno_gamma = (const float*)d_in[13];
    const float* bno_beta  = (const float*)d_in[14];
    const float* bno_mean  = (const float*)d_in[15];
    const float* bno_var   = (const float*)d_in[16];
    const float* out_W     = (const float*)d_in[17];
    const float* out_b     = (const float*)d_in[18];
    float* out = (float*)d_out;

    k_norms<<<2, 256>>>(emb, att_em_i, att_em_j);
    k_cos<<<dim3(Nn / 64, Nn / 32), 256>>>(emb);
    k_xl<<<BN_TOTAL / 64, 256>>>(data, lin_W, att_i, att_j);
    k_topk<<<Nn / 4, 128>>>();
    k_attn<<<BN_TOTAL / 16, 256>>>(emb, gnn_bias,
                                   bn1_gamma, bn1_beta, bn1_mean, bn1_var,
                                   bno_gamma, bno_beta, bno_mean, bno_var,
                                   out_W, out_b, out);
}